// round 13
// baseline (speedup 1.0000x reference)
#include <cuda_runtime.h>
#include <cuda_fp16.h>
#include <cstdint>
#include <cstddef>

#define BB   8
#define TT   2048
#define NN   1024
#define MTOT (BB*TT)      // 16384

#define BK 64             // 64 halves = 128B row per k-chunk
#define NCH (NN/BK)       // 16 k-chunks

#define CT 16
#define NC (TT/CT)        // 128

// ---- scratch (device globals; no runtime allocation allowed) ----
__device__ __align__(256) __half g_rh [ (size_t)MTOT*NN ];      // fp16 r
__device__ __align__(256) __half g_xih[ (size_t)MTOT*NN ];      // fp16 xi
__device__ __align__(256) __half g_ogh[ (size_t)MTOT*NN ];      // fp16 og
__device__ __align__(256) __half g_xh [ (size_t)MTOT*NN ];      // fp16 x
__device__ __align__(256) __half g_yh [ (size_t)MTOT*NN ];      // fp16 y
__device__ __align__(256) __half g_wh[5][ (size_t)NN*NN ];      // fp16 weights
__device__ float g_cA[ (size_t)BB*NC*NN ];
__device__ float g_cB[ (size_t)BB*NC*NN ];
__device__ float g_cH[ (size_t)BB*NC*NN ];

// ================= helpers =================

__device__ __forceinline__ uint32_t smem_u32(const void* p) {
    uint32_t a;
    asm("{ .reg .u64 t; cvta.to.shared.u64 t, %1; cvt.u32.u64 %0, t; }" : "=r"(a) : "l"(p));
    return a;
}

#define CP_ASYNC16(dst, src) \
    asm volatile("cp.async.cg.shared.global [%0], [%1], 16;" :: "r"(dst), "l"(src) : "memory")
#define CP_COMMIT() asm volatile("cp.async.commit_group;" ::: "memory")
#define CP_WAIT(n)  asm volatile("cp.async.wait_group %0;" :: "n"(n) : "memory")

__device__ __forceinline__ void ldsm4(uint32_t a[4], uint32_t addr) {
    asm volatile("ldmatrix.sync.aligned.m8n8.x4.shared.b16 {%0,%1,%2,%3}, [%4];"
        : "=r"(a[0]), "=r"(a[1]), "=r"(a[2]), "=r"(a[3]) : "r"(addr));
}

__device__ __forceinline__ void mma16(float c[4], const uint32_t a[4], const uint32_t b[2]) {
    asm volatile(
        "mma.sync.aligned.m16n8k16.row.col.f32.f16.f16.f32 "
        "{%0,%1,%2,%3}, {%4,%5,%6,%7}, {%8,%9}, {%0,%1,%2,%3};\n"
        : "+f"(c[0]), "+f"(c[1]), "+f"(c[2]), "+f"(c[3])
        : "r"(a[0]), "r"(a[1]), "r"(a[2]), "r"(a[3]),
          "r"(b[0]), "r"(b[1]));
}

__device__ __forceinline__ float sigmoidf_fast(float x) {
    return 1.0f / (1.0f + __expf(-x));
}

// ================= fused fp16 conversion (x + 5 weights, one launch) =================

#define XN8 (MTOT * NN / 8)          // 2,097,152 units of 8 halves
#define WN8 (NN * NN / 8)            // 131,072 per weight
#define TOTN8 (XN8 + 5 * WN8)

__global__ void cvt_all(const float* __restrict__ x,
                        const float* __restrict__ w0, const float* __restrict__ w1,
                        const float* __restrict__ w2, const float* __restrict__ w3,
                        const float* __restrict__ w4,
                        __half* __restrict__ xh, __half* __restrict__ wh)
{
    int i = blockIdx.x * blockDim.x + threadIdx.x;
    const int stride = gridDim.x * blockDim.x;
    for (; i < TOTN8; i += stride) {
        const float* src;
        __half* dst;
        int k;
        if (i < XN8) { src = x; dst = xh; k = i; }
        else {
            const int wi = (i - XN8) / WN8;
            k = (i - XN8) - wi * WN8;
            switch (wi) {
                case 0: src = w0; break;
                case 1: src = w1; break;
                case 2: src = w2; break;
                case 3: src = w3; break;
                default: src = w4; break;
            }
            dst = wh + (size_t)wi * NN * NN;
        }
        float4 v0 = ((const float4*)src)[2 * k];
        float4 v1 = ((const float4*)src)[2 * k + 1];
        uint4 o;
        half2 h;
        h = __floats2half2_rn(v0.x, v0.y); o.x = *(uint32_t*)&h;
        h = __floats2half2_rn(v0.z, v0.w); o.y = *(uint32_t*)&h;
        h = __floats2half2_rn(v1.x, v1.y); o.z = *(uint32_t*)&h;
        h = __floats2half2_rn(v1.z, v1.w); o.w = *(uint32_t*)&h;
        ((uint4*)dst)[k] = o;
    }
}

// ===== merged projection kernel (512 threads, warp tile 64x32, 4 sub-stages) =====
// grid.z = 0:  out_xi = (A@Wi^T) * sigmoid(A@Wig^T + big)          (fp16 out)
// grid.z = 1:  out_r  = sigmoid(A@Wr^T + br) (fp16), out_og = sigmoid(A@Wog^T + bog) (fp16)

#define STG2 49152   // 16KB A + 16KB B1 + 16KB B2 per sub-stage

__global__ __launch_bounds__(512, 1)
void gemm_proj(const __half* __restrict__ A,
               const __half* __restrict__ Wi,  const __half* __restrict__ Wig,
               const __half* __restrict__ Wr,  const __half* __restrict__ Wog,
               const float* __restrict__ big, const float* __restrict__ br,
               const float* __restrict__ bog,
               __half* __restrict__ out_r, __half* __restrict__ out_xi,
               __half* __restrict__ out_og)
{
    extern __shared__ char smem[];
    const uint32_t sb = smem_u32(smem);

    const int tid  = threadIdx.x;
    const int warp = tid >> 5, lane = tid & 31;
    const int task = blockIdx.z;
    const __half* W1 = task ? Wr  : Wi;
    const __half* W2 = task ? Wog : Wig;
    const int m0 = blockIdx.y * 128;
    const int n0 = blockIdx.x * 128;
    const int p  = warp >> 3;
    const int w8 = warp & 7;
    const int wm = (w8 & 1) * 64;
    const int wn = (w8 >> 1) * 32;
    const int g  = lane >> 2, t4 = lane & 3;
    const int r8 = lane & 7;
    const int qa   = (lane >> 4) & 1;
    const int q1   = (lane >> 3) & 1;
    const int nsel = (lane >> 4) & 1;

    float c[4][4][4];
    #pragma unroll
    for (int mt = 0; mt < 4; mt++)
        #pragma unroll
        for (int nt = 0; nt < 4; nt++)
            #pragma unroll
            for (int i = 0; i < 4; i++) c[mt][nt][i] = 0.f;

    // loads: 384 rows x 8 16B-groups / 512 thr = 6 each
    const __half* srcp[6];
    uint32_t dsto[6];
    #pragma unroll
    for (int j = 0; j < 6; j++) {
        const int gidx = tid + 512 * j;
        const int rr = gidx >> 3, cc = gidx & 7;
        const __half* base;
        int row;
        if (rr < 128)      { base = A;  row = m0 + rr; }
        else if (rr < 256) { base = W1; row = n0 + rr - 128; }
        else               { base = W2; row = n0 + rr - 256; }
        srcp[j] = base + (size_t)row * NN + cc * 8;
        dsto[j] = (uint32_t)rr * 128 + (((uint32_t)(cc ^ (rr & 7))) << 4);
    }

    auto load_stage = [&](int s, int kt) {
        const uint32_t off = sb + s * STG2;
        #pragma unroll
        for (int j = 0; j < 6; j++)
            CP_ASYNC16(off + dsto[j], srcp[j] + kt);
        CP_COMMIT();
    };

    const uint32_t bbase = 16384 + (uint32_t)p * 16384;
    uint32_t rowoffA[4], rowoffB[2];
    #pragma unroll
    for (int mt = 0; mt < 4; mt++)
        rowoffA[mt] = (uint32_t)(wm + mt * 16 + q1 * 8 + r8) * 128;
    #pragma unroll
    for (int ntp = 0; ntp < 2; ntp++)
        rowoffB[ntp] = (uint32_t)(wn + (ntp * 2 + nsel) * 8 + r8) * 128 + bbase;

    load_stage(0, 0);
    load_stage(1, BK);

    int sub = 0;
    for (int i = 0; i < NCH / 2; i++) {
        CP_WAIT(0);
        __syncthreads();
        if (i < NCH / 2 - 1) {
            load_stage((sub + 2) & 3, (2 * i + 2) * BK);
            load_stage((sub + 3) & 3, (2 * i + 3) * BK);
        }
        #pragma unroll
        for (int hf = 0; hf < 2; hf++) {
            const uint32_t sab = sb + ((sub + hf) & 3) * STG2;
            #pragma unroll
            for (int ks = 0; ks < 4; ks++) {
                uint32_t a[4][4];
                const uint32_t kga = (uint32_t)(((ks << 1) + qa) ^ r8) << 4;
                #pragma unroll
                for (int mt = 0; mt < 4; mt++)
                    ldsm4(a[mt], sab + rowoffA[mt] + kga);
                uint32_t b[4][2];
                const uint32_t kgb = (uint32_t)(((ks << 1) + q1) ^ r8) << 4;
                #pragma unroll
                for (int ntp = 0; ntp < 2; ntp++) {
                    uint32_t bb[4];
                    ldsm4(bb, sab + rowoffB[ntp] + kgb);
                    b[2 * ntp][0] = bb[0]; b[2 * ntp][1] = bb[1];
                    b[2 * ntp + 1][0] = bb[2]; b[2 * ntp + 1][1] = bb[3];
                }
                #pragma unroll
                for (int mt = 0; mt < 4; mt++)
                    #pragma unroll
                    for (int nt = 0; nt < 4; nt++)
                        mma16(c[mt][nt], a[mt], b[nt]);
            }
        }
        sub = (sub + 2) & 3;
    }

    if (task == 0) {
        // xi = prod1 * sigmoid(prod2 + big), fp16 out; smem exchange
        __syncthreads();   // epilogue scratch overlaps stage buffers
        float* sg = (float*)smem;
        if (p == 1) {
            #pragma unroll
            for (int mt = 0; mt < 4; mt++)
                #pragma unroll
                for (int nt = 0; nt < 4; nt++) {
                    const int col = wn + nt * 8 + 2 * t4;
                    const float b0 = big[n0 + col], b1 = big[n0 + col + 1];
                    #pragma unroll
                    for (int h = 0; h < 2; h++) {
                        const int row = wm + mt * 16 + g + h * 8;
                        sg[row * 132 + col]     = sigmoidf_fast(c[mt][nt][2 * h + 0] + b0);
                        sg[row * 132 + col + 1] = sigmoidf_fast(c[mt][nt][2 * h + 1] + b1);
                    }
                }
        }
        __syncthreads();
        if (p == 0) {
            #pragma unroll
            for (int mt = 0; mt < 4; mt++)
                #pragma unroll
                for (int nt = 0; nt < 4; nt++) {
                    const int col = wn + nt * 8 + 2 * t4;
                    #pragma unroll
                    for (int h = 0; h < 2; h++) {
                        const int row = wm + mt * 16 + g + h * 8;
                        const float v0 = c[mt][nt][2 * h + 0] * sg[row * 132 + col];
                        const float v1 = c[mt][nt][2 * h + 1] * sg[row * 132 + col + 1];
                        *(half2*)(out_xi + (size_t)(m0 + row) * NN + n0 + col) =
                            __floats2half2_rn(v0, v1);
                    }
                }
        }
    } else {
        // p==0: r = sigmoid(prod1 + br);  p==1: og = sigmoid(prod2 + bog)  (both fp16)
        const float* bias = p ? bog : br;
        __half* dst = p ? out_og : out_r;
        #pragma unroll
        for (int mt = 0; mt < 4; mt++)
            #pragma unroll
            for (int nt = 0; nt < 4; nt++) {
                const int col = n0 + wn + nt * 8 + 2 * t4;
                const float bb0 = bias[col], bb1 = bias[col + 1];
                #pragma unroll
                for (int h = 0; h < 2; h++) {
                    const int row = m0 + wm + mt * 16 + g + h * 8;
                    const float v0 = sigmoidf_fast(c[mt][nt][2 * h + 0] + bb0);
                    const float v1 = sigmoidf_fast(c[mt][nt][2 * h + 1] + bb1);
                    *(half2*)(dst + (size_t)row * NN + col) = __floats2half2_rn(v0, v1);
                }
            }
    }
}

// ===== NB1W GEMM: out = A@W^T. 512 threads, BM=128, BN=256, warp tile 64x32. =====

#define STG1 49152   // 16KB A + 32KB B per sub-stage

__global__ __launch_bounds__(512, 1)
void gemm_nb1w(const __half* __restrict__ A,
               const __half* __restrict__ W,
               float* __restrict__ out)
{
    extern __shared__ char smem[];
    const uint32_t sb = smem_u32(smem);

    const int tid  = threadIdx.x;
    const int warp = tid >> 5, lane = tid & 31;
    const int m0 = blockIdx.y * 128;
    const int n0 = blockIdx.x * 256;
    const int wm = (warp & 1) * 64;
    const int wn = (warp >> 1) * 32;
    const int g  = lane >> 2, t4 = lane & 3;
    const int r8 = lane & 7;
    const int qa   = (lane >> 4) & 1;
    const int q1   = (lane >> 3) & 1;
    const int nsel = (lane >> 4) & 1;

    float c[4][4][4];
    #pragma unroll
    for (int mt = 0; mt < 4; mt++)
        #pragma unroll
        for (int nt = 0; nt < 4; nt++)
            #pragma unroll
            for (int i = 0; i < 4; i++) c[mt][nt][i] = 0.f;

    const __half* srcp[6];
    uint32_t dsto[6];
    #pragma unroll
    for (int j = 0; j < 6; j++) {
        const int gidx = tid + 512 * j;
        const int rr = gidx >> 3, cc = gidx & 7;
        const __half* base;
        int row;
        if (rr < 128) { base = A; row = m0 + rr; }
        else          { base = W; row = n0 + rr - 128; }
        srcp[j] = base + (size_t)row * NN + cc * 8;
        dsto[j] = (uint32_t)rr * 128 + (((uint32_t)(cc ^ (rr & 7))) << 4);
    }

    auto load_stage = [&](int s, int kt) {
        const uint32_t off = sb + s * STG1;
        #pragma unroll
        for (int j = 0; j < 6; j++)
            CP_ASYNC16(off + dsto[j], srcp[j] + kt);
        CP_COMMIT();
    };

    uint32_t rowoffA[4], rowoffB[2];
    #pragma unroll
    for (int mt = 0; mt < 4; mt++)
        rowoffA[mt] = (uint32_t)(wm + mt * 16 + q1 * 8 + r8) * 128;
    #pragma unroll
    for (int ntp = 0; ntp < 2; ntp++)
        rowoffB[ntp] = (uint32_t)(wn + (ntp * 2 + nsel) * 8 + r8) * 128 + 16384;

    load_stage(0, 0);
    load_stage(1, BK);

    int sub = 0;
    for (int i = 0; i < NCH / 2; i++) {
        CP_WAIT(0);
        __syncthreads();
        if (i < NCH / 2 - 1) {
            load_stage((sub + 2) & 3, (2 * i + 2) * BK);
            load_stage((sub + 3) & 3, (2 * i + 3) * BK);
        }
        #pragma unroll
        for (int hf = 0; hf < 2; hf++) {
            const uint32_t sab = sb + ((sub + hf) & 3) * STG1;
            #pragma unroll
            for (int ks = 0; ks < 4; ks++) {
                uint32_t a[4][4];
                const uint32_t kga = (uint32_t)(((ks << 1) + qa) ^ r8) << 4;
                #pragma unroll
                for (int mt = 0; mt < 4; mt++)
                    ldsm4(a[mt], sab + rowoffA[mt] + kga);
                uint32_t b[4][2];
                const uint32_t kgb = (uint32_t)(((ks << 1) + q1) ^ r8) << 4;
                #pragma unroll
                for (int ntp = 0; ntp < 2; ntp++) {
                    uint32_t bb[4];
                    ldsm4(bb, sab + rowoffB[ntp] + kgb);
                    b[2 * ntp][0] = bb[0]; b[2 * ntp][1] = bb[1];
                    b[2 * ntp + 1][0] = bb[2]; b[2 * ntp + 1][1] = bb[3];
                }
                #pragma unroll
                for (int mt = 0; mt < 4; mt++)
                    #pragma unroll
                    for (int nt = 0; nt < 4; nt++)
                        mma16(c[mt][nt], a[mt], b[nt]);
            }
        }
        sub = (sub + 2) & 3;
    }

    #pragma unroll
    for (int mt = 0; mt < 4; mt++)
        #pragma unroll
        for (int nt = 0; nt < 4; nt++) {
            const int col = n0 + wn + nt * 8 + 2 * t4;
            #pragma unroll
            for (int h = 0; h < 2; h++) {
                const int row = m0 + wm + mt * 16 + g + h * 8;
                *(float2*)(out + (size_t)row * NN + col) =
                    make_float2(c[mt][nt][2 * h + 0], c[mt][nt][2 * h + 1]);
            }
        }
}

// ================= chunked associative scan (CT=16, 2 channels/thread, fp16 streams) ====

__global__ __launch_bounds__(512)
void scan_passA()
{
    const int bj = blockIdx.x;            // b*NC + j, 1024 blocks
    const int b  = bj / NC, j = bj % NC;
    const int m2 = threadIdx.x * 2;
    const size_t base = ((size_t)b * TT + (size_t)j * CT) * NN + m2;
    float2 Aacc = make_float2(1.f, 1.f);
    float2 h    = make_float2(0.f, 0.f);
    #pragma unroll
    for (int t = 0; t < CT; t++) {
        const size_t o = base + (size_t)t * NN;
        const float2 rv = __half22float2(*(const __half2*)(g_rh  + o));
        const float2 xv = __half22float2(*(const __half2*)(g_xih + o));
        h.x = h.x * rv.x + xv.x;
        h.y = h.y * rv.y + xv.y;
        Aacc.x *= rv.x;
        Aacc.y *= rv.y;
    }
    const size_t ci = (size_t)bj * NN + m2;
    *(float2*)(g_cA + ci) = Aacc;
    *(float2*)(g_cB + ci) = h;
}

__global__ __launch_bounds__(512)
void scan_mid(const float* __restrict__ mem)
{
    const int b  = blockIdx.x;
    const int m2 = threadIdx.x * 2;
    float2 h = *(const float2*)(mem + b * NN + m2);
    #pragma unroll 8
    for (int j = 0; j < NC; j++) {
        const size_t ci = (size_t)(b * NC + j) * NN + m2;
        *(float2*)(g_cH + ci) = h;
        const float2 a  = *(const float2*)(g_cA + ci);
        const float2 bv = *(const float2*)(g_cB + ci);
        h.x = a.x * h.x + bv.x;
        h.y = a.y * h.y + bv.y;
    }
}

__global__ __launch_bounds__(512)
void scan_passB(float* __restrict__ memout)
{
    const int bj = blockIdx.x;
    const int b  = bj / NC, j = bj % NC;
    const int m2 = threadIdx.x * 2;
    const size_t base = ((size_t)b * TT + (size_t)j * CT) * NN + m2;
    float2 h = *(const float2*)(g_cH + (size_t)bj * NN + m2);
    #pragma unroll
    for (int t = 0; t < CT; t++) {
        const size_t o = base + (size_t)t * NN;
        const float2 rv = __half22float2(*(const __half2*)(g_rh  + o));
        const float2 xv = __half22float2(*(const __half2*)(g_xih + o));
        const float2 ov = __half22float2(*(const __half2*)(g_ogh + o));
        h.x = h.x * rv.x + xv.x;
        h.y = h.y * rv.y + xv.y;
        const float y0 = (h.x / (1.f + fabsf(h.x))) * ov.x;
        const float y1 = (h.y / (1.f + fabsf(h.y))) * ov.y;
        *(half2*)(g_yh + o) = __floats2half2_rn(y0, y1);
    }
    if (j == NC - 1) *(float2*)(memout + b * NN + m2) = h;
}

// ================= host =================

extern "C" void kernel_launch(void* const* d_in, const int* in_sizes, int n_in,
                              void* d_out, int out_size)
{
    const float* x     = (const float*)d_in[0];
    const float* mem   = (const float*)d_in[1];
    const float* wr_w  = (const float*)d_in[2];
    const float* wr_b  = (const float*)d_in[3];
    const float* wi_w  = (const float*)d_in[4];
    const float* wig_w = (const float*)d_in[5];
    const float* wig_b = (const float*)d_in[6];
    const float* wog_w = (const float*)d_in[7];
    const float* wog_b = (const float*)d_in[8];
    const float* wo_w  = (const float*)d_in[9];

    float* out     = (float*)d_out;
    float* y_out   = out;
    float* mem_out = out + (size_t)MTOT * NN;

    __half *p_rh, *p_xih, *p_ogh, *p_xh, *p_yh, *p_wh;
    cudaGetSymbolAddress((void**)&p_rh,  g_rh);
    cudaGetSymbolAddress((void**)&p_xih, g_xih);
    cudaGetSymbolAddress((void**)&p_ogh, g_ogh);
    cudaGetSymbolAddress((void**)&p_xh,  g_xh);
    cudaGetSymbolAddress((void**)&p_yh,  g_yh);
    cudaGetSymbolAddress((void**)&p_wh,  g_wh);

    __half* wh_r  = p_wh + 0 * (size_t)NN * NN;
    __half* wh_i  = p_wh + 1 * (size_t)NN * NN;
    __half* wh_ig = p_wh + 2 * (size_t)NN * NN;
    __half* wh_og = p_wh + 3 * (size_t)NN * NN;
    __half* wh_o  = p_wh + 4 * (size_t)NN * NN;

    constexpr int SMEM = 4 * STG2;   // 192KB, 4 sub-stages
    cudaFuncSetAttribute(gemm_proj, cudaFuncAttributeMaxDynamicSharedMemorySize, SMEM);
    cudaFuncSetAttribute(gemm_nb1w, cudaFuncAttributeMaxDynamicSharedMemorySize, SMEM);

    dim3 ggp(NN / 128, MTOT / 128, 2);   // (8, 128, 2)
    dim3 gg1(NN / 256, MTOT / 128);      // (4, 128)

    cvt_all<<<2688, 256>>>(x, wr_w, wi_w, wig_w, wog_w, wo_w, p_xh, p_wh);  // 0
    gemm_proj<<<ggp, 512, SMEM>>>(p_xh, wh_i, wh_ig, wh_r, wh_og,           // 1
                                  wig_b, wr_b, wog_b, p_rh, p_xih, p_ogh);
    scan_passA<<<BB * NC, 512>>>();                                         // 2
    scan_mid  <<<BB, 512>>>(mem);                                           // 3 (PROFILED)
    scan_passB<<<BB * NC, 512>>>(mem_out);                                  // 4
    gemm_nb1w<<<gg1, 512, SMEM>>>(p_yh, wh_o, y_out);                       // 5
}

// round 14
// speedup vs baseline: 1.0012x; 1.0012x over previous
#include <cuda_runtime.h>
#include <cuda_fp16.h>
#include <cstdint>
#include <cstddef>

#define BB   8
#define TT   2048
#define NN   1024
#define MTOT (BB*TT)      // 16384

#define BK 64             // 64 halves = 128B row per k-chunk
#define NCH (NN/BK)       // 16 k-chunks

#define CT 16
#define NC (TT/CT)        // 128

// ---- scratch (device globals; no runtime allocation allowed) ----
__device__ __align__(256) __half g_rh [ (size_t)MTOT*NN ];      // fp16 r
__device__ __align__(256) __half g_xih[ (size_t)MTOT*NN ];      // fp16 xi
__device__ __align__(256) __half g_ogh[ (size_t)MTOT*NN ];      // fp16 og
__device__ __align__(256) __half g_xh [ (size_t)MTOT*NN ];      // fp16 x
__device__ __align__(256) __half g_yh [ (size_t)MTOT*NN ];      // fp16 y
__device__ __align__(256) __half g_wh[5][ (size_t)NN*NN ];      // fp16 weights
__device__ float g_cA[ (size_t)BB*NC*NN ];
__device__ float g_cB[ (size_t)BB*NC*NN ];
__device__ float g_cH[ (size_t)BB*NC*NN ];

// ================= helpers =================

__device__ __forceinline__ uint32_t smem_u32(const void* p) {
    uint32_t a;
    asm("{ .reg .u64 t; cvta.to.shared.u64 t, %1; cvt.u32.u64 %0, t; }" : "=r"(a) : "l"(p));
    return a;
}

#define CP_ASYNC16(dst, src) \
    asm volatile("cp.async.cg.shared.global [%0], [%1], 16;" :: "r"(dst), "l"(src) : "memory")
#define CP_COMMIT() asm volatile("cp.async.commit_group;" ::: "memory")
#define CP_WAIT(n)  asm volatile("cp.async.wait_group %0;" :: "n"(n) : "memory")

__device__ __forceinline__ void ldsm4(uint32_t a[4], uint32_t addr) {
    asm volatile("ldmatrix.sync.aligned.m8n8.x4.shared.b16 {%0,%1,%2,%3}, [%4];"
        : "=r"(a[0]), "=r"(a[1]), "=r"(a[2]), "=r"(a[3]) : "r"(addr));
}

__device__ __forceinline__ void mma16(float c[4], const uint32_t a[4], const uint32_t b[2]) {
    asm volatile(
        "mma.sync.aligned.m16n8k16.row.col.f32.f16.f16.f32 "
        "{%0,%1,%2,%3}, {%4,%5,%6,%7}, {%8,%9}, {%0,%1,%2,%3};\n"
        : "+f"(c[0]), "+f"(c[1]), "+f"(c[2]), "+f"(c[3])
        : "r"(a[0]), "r"(a[1]), "r"(a[2]), "r"(a[3]),
          "r"(b[0]), "r"(b[1]));
}

__device__ __forceinline__ float sigmoidf_fast(float x) {
    return 1.0f / (1.0f + __expf(-x));
}

// ================= fused fp16 conversion (x + 5 weights, one launch) =================

#define XN8 (MTOT * NN / 8)          // 2,097,152 units of 8 halves
#define WN8 (NN * NN / 8)            // 131,072 per weight
#define TOTN8 (XN8 + 5 * WN8)

__global__ void cvt_all(const float* __restrict__ x,
                        const float* __restrict__ w0, const float* __restrict__ w1,
                        const float* __restrict__ w2, const float* __restrict__ w3,
                        const float* __restrict__ w4,
                        __half* __restrict__ xh, __half* __restrict__ wh)
{
    int i = blockIdx.x * blockDim.x + threadIdx.x;
    const int stride = gridDim.x * blockDim.x;
    for (; i < TOTN8; i += stride) {
        const float* src;
        __half* dst;
        int k;
        if (i < XN8) { src = x; dst = xh; k = i; }
        else {
            const int wi = (i - XN8) / WN8;
            k = (i - XN8) - wi * WN8;
            switch (wi) {
                case 0: src = w0; break;
                case 1: src = w1; break;
                case 2: src = w2; break;
                case 3: src = w3; break;
                default: src = w4; break;
            }
            dst = wh + (size_t)wi * NN * NN;
        }
        float4 v0 = ((const float4*)src)[2 * k];
        float4 v1 = ((const float4*)src)[2 * k + 1];
        uint4 o;
        half2 h;
        h = __floats2half2_rn(v0.x, v0.y); o.x = *(uint32_t*)&h;
        h = __floats2half2_rn(v0.z, v0.w); o.y = *(uint32_t*)&h;
        h = __floats2half2_rn(v1.x, v1.y); o.z = *(uint32_t*)&h;
        h = __floats2half2_rn(v1.z, v1.w); o.w = *(uint32_t*)&h;
        ((uint4*)dst)[k] = o;
    }
}

// ===== merged projection kernel (512 threads, warp tile 64x32, 4 sub-stages) =====
// grid.z = 0:  out_xi = (A@Wi^T) * sigmoid(A@Wig^T + big)          (fp16 out)
// grid.z = 1:  out_r  = sigmoid(A@Wr^T + br) (fp16), out_og = sigmoid(A@Wog^T + bog) (fp16)

#define STG2 49152   // 16KB A + 16KB B1 + 16KB B2 per sub-stage

__global__ __launch_bounds__(512, 1)
void gemm_proj(const __half* __restrict__ A,
               const __half* __restrict__ Wi,  const __half* __restrict__ Wig,
               const __half* __restrict__ Wr,  const __half* __restrict__ Wog,
               const float* __restrict__ big, const float* __restrict__ br,
               const float* __restrict__ bog,
               __half* __restrict__ out_r, __half* __restrict__ out_xi,
               __half* __restrict__ out_og)
{
    extern __shared__ char smem[];
    const uint32_t sb = smem_u32(smem);

    const int tid  = threadIdx.x;
    const int warp = tid >> 5, lane = tid & 31;
    const int task = blockIdx.z;
    const __half* W1 = task ? Wr  : Wi;
    const __half* W2 = task ? Wog : Wig;
    const int m0 = blockIdx.y * 128;
    const int n0 = blockIdx.x * 128;
    const int p  = warp >> 3;
    const int w8 = warp & 7;
    const int wm = (w8 & 1) * 64;
    const int wn = (w8 >> 1) * 32;
    const int g  = lane >> 2, t4 = lane & 3;
    const int r8 = lane & 7;
    const int qa   = (lane >> 4) & 1;
    const int q1   = (lane >> 3) & 1;
    const int nsel = (lane >> 4) & 1;

    float c[4][4][4];
    #pragma unroll
    for (int mt = 0; mt < 4; mt++)
        #pragma unroll
        for (int nt = 0; nt < 4; nt++)
            #pragma unroll
            for (int i = 0; i < 4; i++) c[mt][nt][i] = 0.f;

    // loads: 384 rows x 8 16B-groups / 512 thr = 6 each
    const __half* srcp[6];
    uint32_t dsto[6];
    #pragma unroll
    for (int j = 0; j < 6; j++) {
        const int gidx = tid + 512 * j;
        const int rr = gidx >> 3, cc = gidx & 7;
        const __half* base;
        int row;
        if (rr < 128)      { base = A;  row = m0 + rr; }
        else if (rr < 256) { base = W1; row = n0 + rr - 128; }
        else               { base = W2; row = n0 + rr - 256; }
        srcp[j] = base + (size_t)row * NN + cc * 8;
        dsto[j] = (uint32_t)rr * 128 + (((uint32_t)(cc ^ (rr & 7))) << 4);
    }

    auto load_stage = [&](int s, int kt) {
        const uint32_t off = sb + s * STG2;
        #pragma unroll
        for (int j = 0; j < 6; j++)
            CP_ASYNC16(off + dsto[j], srcp[j] + kt);
        CP_COMMIT();
    };

    const uint32_t bbase = 16384 + (uint32_t)p * 16384;
    uint32_t rowoffA[4], rowoffB[2];
    #pragma unroll
    for (int mt = 0; mt < 4; mt++)
        rowoffA[mt] = (uint32_t)(wm + mt * 16 + q1 * 8 + r8) * 128;
    #pragma unroll
    for (int ntp = 0; ntp < 2; ntp++)
        rowoffB[ntp] = (uint32_t)(wn + (ntp * 2 + nsel) * 8 + r8) * 128 + bbase;

    load_stage(0, 0);
    load_stage(1, BK);

    int sub = 0;
    for (int i = 0; i < NCH / 2; i++) {
        CP_WAIT(0);
        __syncthreads();
        if (i < NCH / 2 - 1) {
            load_stage((sub + 2) & 3, (2 * i + 2) * BK);
            load_stage((sub + 3) & 3, (2 * i + 3) * BK);
        }
        #pragma unroll
        for (int hf = 0; hf < 2; hf++) {
            const uint32_t sab = sb + ((sub + hf) & 3) * STG2;
            #pragma unroll
            for (int ks = 0; ks < 4; ks++) {
                uint32_t a[4][4];
                const uint32_t kga = (uint32_t)(((ks << 1) + qa) ^ r8) << 4;
                #pragma unroll
                for (int mt = 0; mt < 4; mt++)
                    ldsm4(a[mt], sab + rowoffA[mt] + kga);
                uint32_t b[4][2];
                const uint32_t kgb = (uint32_t)(((ks << 1) + q1) ^ r8) << 4;
                #pragma unroll
                for (int ntp = 0; ntp < 2; ntp++) {
                    uint32_t bb[4];
                    ldsm4(bb, sab + rowoffB[ntp] + kgb);
                    b[2 * ntp][0] = bb[0]; b[2 * ntp][1] = bb[1];
                    b[2 * ntp + 1][0] = bb[2]; b[2 * ntp + 1][1] = bb[3];
                }
                #pragma unroll
                for (int mt = 0; mt < 4; mt++)
                    #pragma unroll
                    for (int nt = 0; nt < 4; nt++)
                        mma16(c[mt][nt], a[mt], b[nt]);
            }
        }
        sub = (sub + 2) & 3;
    }

    if (task == 0) {
        // xi = prod1 * sigmoid(prod2 + big), fp16 out; smem exchange
        __syncthreads();   // epilogue scratch overlaps stage buffers
        float* sg = (float*)smem;
        if (p == 1) {
            #pragma unroll
            for (int mt = 0; mt < 4; mt++)
                #pragma unroll
                for (int nt = 0; nt < 4; nt++) {
                    const int col = wn + nt * 8 + 2 * t4;
                    const float b0 = big[n0 + col], b1 = big[n0 + col + 1];
                    #pragma unroll
                    for (int h = 0; h < 2; h++) {
                        const int row = wm + mt * 16 + g + h * 8;
                        sg[row * 132 + col]     = sigmoidf_fast(c[mt][nt][2 * h + 0] + b0);
                        sg[row * 132 + col + 1] = sigmoidf_fast(c[mt][nt][2 * h + 1] + b1);
                    }
                }
        }
        __syncthreads();
        if (p == 0) {
            #pragma unroll
            for (int mt = 0; mt < 4; mt++)
                #pragma unroll
                for (int nt = 0; nt < 4; nt++) {
                    const int col = wn + nt * 8 + 2 * t4;
                    #pragma unroll
                    for (int h = 0; h < 2; h++) {
                        const int row = wm + mt * 16 + g + h * 8;
                        const float v0 = c[mt][nt][2 * h + 0] * sg[row * 132 + col];
                        const float v1 = c[mt][nt][2 * h + 1] * sg[row * 132 + col + 1];
                        *(half2*)(out_xi + (size_t)(m0 + row) * NN + n0 + col) =
                            __floats2half2_rn(v0, v1);
                    }
                }
        }
    } else {
        // p==0: r = sigmoid(prod1 + br);  p==1: og = sigmoid(prod2 + bog)  (both fp16)
        const float* bias = p ? bog : br;
        __half* dst = p ? out_og : out_r;
        #pragma unroll
        for (int mt = 0; mt < 4; mt++)
            #pragma unroll
            for (int nt = 0; nt < 4; nt++) {
                const int col = n0 + wn + nt * 8 + 2 * t4;
                const float bb0 = bias[col], bb1 = bias[col + 1];
                #pragma unroll
                for (int h = 0; h < 2; h++) {
                    const int row = m0 + wm + mt * 16 + g + h * 8;
                    const float v0 = sigmoidf_fast(c[mt][nt][2 * h + 0] + bb0);
                    const float v1 = sigmoidf_fast(c[mt][nt][2 * h + 1] + bb1);
                    *(half2*)(dst + (size_t)row * NN + col) = __floats2half2_rn(v0, v1);
                }
            }
    }
}

// ===== NB1W GEMM: out = A@W^T. 512 threads, BM=128, BN=256, warp tile 64x32. =====

#define STG1 49152   // 16KB A + 32KB B per sub-stage

__global__ __launch_bounds__(512, 1)
void gemm_nb1w(const __half* __restrict__ A,
               const __half* __restrict__ W,
               float* __restrict__ out)
{
    extern __shared__ char smem[];
    const uint32_t sb = smem_u32(smem);

    const int tid  = threadIdx.x;
    const int warp = tid >> 5, lane = tid & 31;
    const int m0 = blockIdx.y * 128;
    const int n0 = blockIdx.x * 256;
    const int wm = (warp & 1) * 64;
    const int wn = (warp >> 1) * 32;
    const int g  = lane >> 2, t4 = lane & 3;
    const int r8 = lane & 7;
    const int qa   = (lane >> 4) & 1;
    const int q1   = (lane >> 3) & 1;
    const int nsel = (lane >> 4) & 1;

    float c[4][4][4];
    #pragma unroll
    for (int mt = 0; mt < 4; mt++)
        #pragma unroll
        for (int nt = 0; nt < 4; nt++)
            #pragma unroll
            for (int i = 0; i < 4; i++) c[mt][nt][i] = 0.f;

    const __half* srcp[6];
    uint32_t dsto[6];
    #pragma unroll
    for (int j = 0; j < 6; j++) {
        const int gidx = tid + 512 * j;
        const int rr = gidx >> 3, cc = gidx & 7;
        const __half* base;
        int row;
        if (rr < 128) { base = A; row = m0 + rr; }
        else          { base = W; row = n0 + rr - 128; }
        srcp[j] = base + (size_t)row * NN + cc * 8;
        dsto[j] = (uint32_t)rr * 128 + (((uint32_t)(cc ^ (rr & 7))) << 4);
    }

    auto load_stage = [&](int s, int kt) {
        const uint32_t off = sb + s * STG1;
        #pragma unroll
        for (int j = 0; j < 6; j++)
            CP_ASYNC16(off + dsto[j], srcp[j] + kt);
        CP_COMMIT();
    };

    uint32_t rowoffA[4], rowoffB[2];
    #pragma unroll
    for (int mt = 0; mt < 4; mt++)
        rowoffA[mt] = (uint32_t)(wm + mt * 16 + q1 * 8 + r8) * 128;
    #pragma unroll
    for (int ntp = 0; ntp < 2; ntp++)
        rowoffB[ntp] = (uint32_t)(wn + (ntp * 2 + nsel) * 8 + r8) * 128 + 16384;

    load_stage(0, 0);
    load_stage(1, BK);

    int sub = 0;
    for (int i = 0; i < NCH / 2; i++) {
        CP_WAIT(0);
        __syncthreads();
        if (i < NCH / 2 - 1) {
            load_stage((sub + 2) & 3, (2 * i + 2) * BK);
            load_stage((sub + 3) & 3, (2 * i + 3) * BK);
        }
        #pragma unroll
        for (int hf = 0; hf < 2; hf++) {
            const uint32_t sab = sb + ((sub + hf) & 3) * STG1;
            #pragma unroll
            for (int ks = 0; ks < 4; ks++) {
                uint32_t a[4][4];
                const uint32_t kga = (uint32_t)(((ks << 1) + qa) ^ r8) << 4;
                #pragma unroll
                for (int mt = 0; mt < 4; mt++)
                    ldsm4(a[mt], sab + rowoffA[mt] + kga);
                uint32_t b[4][2];
                const uint32_t kgb = (uint32_t)(((ks << 1) + q1) ^ r8) << 4;
                #pragma unroll
                for (int ntp = 0; ntp < 2; ntp++) {
                    uint32_t bb[4];
                    ldsm4(bb, sab + rowoffB[ntp] + kgb);
                    b[2 * ntp][0] = bb[0]; b[2 * ntp][1] = bb[1];
                    b[2 * ntp + 1][0] = bb[2]; b[2 * ntp + 1][1] = bb[3];
                }
                #pragma unroll
                for (int mt = 0; mt < 4; mt++)
                    #pragma unroll
                    for (int nt = 0; nt < 4; nt++)
                        mma16(c[mt][nt], a[mt], b[nt]);
            }
        }
        sub = (sub + 2) & 3;
    }

    #pragma unroll
    for (int mt = 0; mt < 4; mt++)
        #pragma unroll
        for (int nt = 0; nt < 4; nt++) {
            const int col = n0 + wn + nt * 8 + 2 * t4;
            #pragma unroll
            for (int h = 0; h < 2; h++) {
                const int row = m0 + wm + mt * 16 + g + h * 8;
                *(float2*)(out + (size_t)row * NN + col) =
                    make_float2(c[mt][nt][2 * h + 0], c[mt][nt][2 * h + 1]);
            }
        }
}

// ================= chunked associative scan (CT=16, fp16 streams) =================

__global__ __launch_bounds__(512)
void scan_passA()
{
    const int bj = blockIdx.x;            // b*NC + j, 1024 blocks
    const int b  = bj / NC, j = bj % NC;
    const int m2 = threadIdx.x * 2;
    const size_t base = ((size_t)b * TT + (size_t)j * CT) * NN + m2;
    float2 Aacc = make_float2(1.f, 1.f);
    float2 h    = make_float2(0.f, 0.f);
    #pragma unroll
    for (int t = 0; t < CT; t++) {
        const size_t o = base + (size_t)t * NN;
        const float2 rv = __half22float2(*(const __half2*)(g_rh  + o));
        const float2 xv = __half22float2(*(const __half2*)(g_xih + o));
        h.x = h.x * rv.x + xv.x;
        h.y = h.y * rv.y + xv.y;
        Aacc.x *= rv.x;
        Aacc.y *= rv.y;
    }
    const size_t ci = (size_t)bj * NN + m2;
    *(float2*)(g_cA + ci) = Aacc;
    *(float2*)(g_cB + ci) = h;
}

// parallel chunk-prefix: 1 channel per thread, 128 blocks (8 batches x 16 groups)
__global__ __launch_bounds__(64)
void scan_mid(const float* __restrict__ mem)
{
    const int b = blockIdx.x;
    const int m = blockIdx.y * 64 + threadIdx.x;
    float h = mem[b * NN + m];
    #pragma unroll 8
    for (int j = 0; j < NC; j++) {
        const size_t ci = (size_t)(b * NC + j) * NN + m;
        g_cH[ci] = h;
        h = g_cA[ci] * h + g_cB[ci];
    }
}

__global__ __launch_bounds__(512)
void scan_passB(float* __restrict__ memout)
{
    const int bj = blockIdx.x;
    const int b  = bj / NC, j = bj % NC;
    const int m2 = threadIdx.x * 2;
    const size_t base = ((size_t)b * TT + (size_t)j * CT) * NN + m2;
    float2 h = *(const float2*)(g_cH + (size_t)bj * NN + m2);
    #pragma unroll
    for (int t = 0; t < CT; t++) {
        const size_t o = base + (size_t)t * NN;
        const float2 rv = __half22float2(*(const __half2*)(g_rh  + o));
        const float2 xv = __half22float2(*(const __half2*)(g_xih + o));
        const float2 ov = __half22float2(*(const __half2*)(g_ogh + o));
        h.x = h.x * rv.x + xv.x;
        h.y = h.y * rv.y + xv.y;
        const float y0 = (h.x / (1.f + fabsf(h.x))) * ov.x;
        const float y1 = (h.y / (1.f + fabsf(h.y))) * ov.y;
        *(half2*)(g_yh + o) = __floats2half2_rn(y0, y1);
    }
    if (j == NC - 1) *(float2*)(memout + b * NN + m2) = h;
}

// ================= host =================

extern "C" void kernel_launch(void* const* d_in, const int* in_sizes, int n_in,
                              void* d_out, int out_size)
{
    const float* x     = (const float*)d_in[0];
    const float* mem   = (const float*)d_in[1];
    const float* wr_w  = (const float*)d_in[2];
    const float* wr_b  = (const float*)d_in[3];
    const float* wi_w  = (const float*)d_in[4];
    const float* wig_w = (const float*)d_in[5];
    const float* wig_b = (const float*)d_in[6];
    const float* wog_w = (const float*)d_in[7];
    const float* wog_b = (const float*)d_in[8];
    const float* wo_w  = (const float*)d_in[9];

    float* out     = (float*)d_out;
    float* y_out   = out;
    float* mem_out = out + (size_t)MTOT * NN;

    __half *p_rh, *p_xih, *p_ogh, *p_xh, *p_yh, *p_wh;
    cudaGetSymbolAddress((void**)&p_rh,  g_rh);
    cudaGetSymbolAddress((void**)&p_xih, g_xih);
    cudaGetSymbolAddress((void**)&p_ogh, g_ogh);
    cudaGetSymbolAddress((void**)&p_xh,  g_xh);
    cudaGetSymbolAddress((void**)&p_yh,  g_yh);
    cudaGetSymbolAddress((void**)&p_wh,  g_wh);

    __half* wh_r  = p_wh + 0 * (size_t)NN * NN;
    __half* wh_i  = p_wh + 1 * (size_t)NN * NN;
    __half* wh_ig = p_wh + 2 * (size_t)NN * NN;
    __half* wh_og = p_wh + 3 * (size_t)NN * NN;
    __half* wh_o  = p_wh + 4 * (size_t)NN * NN;

    constexpr int SMEM = 4 * STG2;   // 192KB, 4 sub-stages
    cudaFuncSetAttribute(gemm_proj, cudaFuncAttributeMaxDynamicSharedMemorySize, SMEM);
    cudaFuncSetAttribute(gemm_nb1w, cudaFuncAttributeMaxDynamicSharedMemorySize, SMEM);

    dim3 ggp(NN / 128, MTOT / 128, 2);   // (8, 128, 2)
    dim3 gg1(NN / 256, MTOT / 128);      // (4, 128)

    cvt_all<<<2688, 256>>>(x, wr_w, wi_w, wig_w, wog_w, wo_w, p_xh, p_wh);  // 0
    gemm_proj<<<ggp, 512, SMEM>>>(p_xh, wh_i, wh_ig, wh_r, wh_og,           // 1
                                  wig_b, wr_b, wog_b, p_rh, p_xih, p_ogh);
    scan_passA<<<BB * NC, 512>>>();                                         // 2
    scan_mid<<<dim3(BB, 16), 64>>>(mem);                                    // 3 (PROFILED)
    scan_passB<<<BB * NC, 512>>>(mem_out);                                  // 4
    gemm_nb1w<<<gg1, 512, SMEM>>>(p_yh, wh_o, y_out);                       // 5
}

// round 15
// speedup vs baseline: 1.0475x; 1.0463x over previous
#include <cuda_runtime.h>
#include <cuda_fp16.h>
#include <cstdint>
#include <cstddef>

#define BB   8
#define TT   2048
#define NN   1024
#define MTOT (BB*TT)      // 16384

#define BK 64             // 64 halves = 128B row per k-chunk
#define NCH (NN/BK)       // 16 k-chunks

#define CT 16
#define NC (TT/CT)        // 128

// ---- scratch (device globals; no runtime allocation allowed) ----
__device__ __align__(256) __half g_rh [ (size_t)MTOT*NN ];      // fp16 r
__device__ __align__(256) __half g_xih[ (size_t)MTOT*NN ];      // fp16 xi
__device__ __align__(256) __half g_ogh[ (size_t)MTOT*NN ];      // fp16 og
__device__ __align__(256) __half g_xh [ (size_t)MTOT*NN ];      // fp16 x
__device__ __align__(256) __half g_yh [ (size_t)MTOT*NN ];      // fp16 y
__device__ __align__(256) __half g_wh[5][ (size_t)NN*NN ];      // fp16 weights
__device__ float g_cA[ (size_t)BB*NC*NN ];
__device__ float g_cB[ (size_t)BB*NC*NN ];
__device__ float g_cH[ (size_t)BB*NC*NN ];

// ================= helpers =================

__device__ __forceinline__ uint32_t smem_u32(const void* p) {
    uint32_t a;
    asm("{ .reg .u64 t; cvta.to.shared.u64 t, %1; cvt.u32.u64 %0, t; }" : "=r"(a) : "l"(p));
    return a;
}

#define CP_ASYNC16(dst, src) \
    asm volatile("cp.async.cg.shared.global [%0], [%1], 16;" :: "r"(dst), "l"(src) : "memory")
#define CP_COMMIT() asm volatile("cp.async.commit_group;" ::: "memory")
#define CP_WAIT(n)  asm volatile("cp.async.wait_group %0;" :: "n"(n) : "memory")

__device__ __forceinline__ void ldsm4(uint32_t a[4], uint32_t addr) {
    asm volatile("ldmatrix.sync.aligned.m8n8.x4.shared.b16 {%0,%1,%2,%3}, [%4];"
        : "=r"(a[0]), "=r"(a[1]), "=r"(a[2]), "=r"(a[3]) : "r"(addr));
}

__device__ __forceinline__ void mma16(float c[4], const uint32_t a[4], const uint32_t b[2]) {
    asm volatile(
        "mma.sync.aligned.m16n8k16.row.col.f32.f16.f16.f32 "
        "{%0,%1,%2,%3}, {%4,%5,%6,%7}, {%8,%9}, {%0,%1,%2,%3};\n"
        : "+f"(c[0]), "+f"(c[1]), "+f"(c[2]), "+f"(c[3])
        : "r"(a[0]), "r"(a[1]), "r"(a[2]), "r"(a[3]),
          "r"(b[0]), "r"(b[1]));
}

__device__ __forceinline__ float sigmoidf_fast(float x) {
    return 1.0f / (1.0f + __expf(-x));
}

// ================= fused fp16 conversion (x + 5 weights, one launch) =================

#define XN8 (MTOT * NN / 8)
#define WN8 (NN * NN / 8)
#define TOTN8 (XN8 + 5 * WN8)

__global__ void cvt_all(const float* __restrict__ x,
                        const float* __restrict__ w0, const float* __restrict__ w1,
                        const float* __restrict__ w2, const float* __restrict__ w3,
                        const float* __restrict__ w4,
                        __half* __restrict__ xh, __half* __restrict__ wh)
{
    int i = blockIdx.x * blockDim.x + threadIdx.x;
    const int stride = gridDim.x * blockDim.x;
    for (; i < TOTN8; i += stride) {
        const float* src;
        __half* dst;
        int k;
        if (i < XN8) { src = x; dst = xh; k = i; }
        else {
            const int wi = (i - XN8) / WN8;
            k = (i - XN8) - wi * WN8;
            switch (wi) {
                case 0: src = w0; break;
                case 1: src = w1; break;
                case 2: src = w2; break;
                case 3: src = w3; break;
                default: src = w4; break;
            }
            dst = wh + (size_t)wi * NN * NN;
        }
        float4 v0 = ((const float4*)src)[2 * k];
        float4 v1 = ((const float4*)src)[2 * k + 1];
        uint4 o;
        half2 h;
        h = __floats2half2_rn(v0.x, v0.y); o.x = *(uint32_t*)&h;
        h = __floats2half2_rn(v0.z, v0.w); o.y = *(uint32_t*)&h;
        h = __floats2half2_rn(v1.x, v1.y); o.z = *(uint32_t*)&h;
        h = __floats2half2_rn(v1.z, v1.w); o.w = *(uint32_t*)&h;
        ((uint4*)dst)[k] = o;
    }
}

// ===== merged projection kernel (512 threads, warp tile 64x32, 4 sub-stages) =====
// grid.z = 0:  out_xi = (A@Wi^T) * sigmoid(A@Wig^T + big)          (fp16 out)
// grid.z = 1:  out_r  = sigmoid(A@Wr^T + br) (fp16), out_og = sigmoid(A@Wog^T + bog) (fp16)

#define STG2 49152   // 16KB A + 16KB B1 + 16KB B2 per sub-stage

__global__ __launch_bounds__(512, 1)
void gemm_proj(const __half* __restrict__ A,
               const __half* __restrict__ Wi,  const __half* __restrict__ Wig,
               const __half* __restrict__ Wr,  const __half* __restrict__ Wog,
               const float* __restrict__ big, const float* __restrict__ br,
               const float* __restrict__ bog,
               __half* __restrict__ out_r, __half* __restrict__ out_xi,
               __half* __restrict__ out_og)
{
    extern __shared__ char smem[];
    const uint32_t sb = smem_u32(smem);

    const int tid  = threadIdx.x;
    const int warp = tid >> 5, lane = tid & 31;
    const int task = blockIdx.z;
    const __half* W1 = task ? Wr  : Wi;
    const __half* W2 = task ? Wog : Wig;
    const int m0 = blockIdx.y * 128;
    const int n0 = blockIdx.x * 128;
    const int p  = warp >> 3;
    const int w8 = warp & 7;
    const int wm = (w8 & 1) * 64;
    const int wn = (w8 >> 1) * 32;
    const int g  = lane >> 2, t4 = lane & 3;
    const int r8 = lane & 7;
    const int qa   = (lane >> 4) & 1;
    const int q1   = (lane >> 3) & 1;
    const int nsel = (lane >> 4) & 1;

    float c[4][4][4];
    #pragma unroll
    for (int mt = 0; mt < 4; mt++)
        #pragma unroll
        for (int nt = 0; nt < 4; nt++)
            #pragma unroll
            for (int i = 0; i < 4; i++) c[mt][nt][i] = 0.f;

    // loads: 384 rows x 8 16B-groups / 512 thr = 6 each
    const __half* srcp[6];
    uint32_t dsto[6];
    #pragma unroll
    for (int j = 0; j < 6; j++) {
        const int gidx = tid + 512 * j;
        const int rr = gidx >> 3, cc = gidx & 7;
        const __half* base;
        int row;
        if (rr < 128)      { base = A;  row = m0 + rr; }
        else if (rr < 256) { base = W1; row = n0 + rr - 128; }
        else               { base = W2; row = n0 + rr - 256; }
        srcp[j] = base + (size_t)row * NN + cc * 8;
        dsto[j] = (uint32_t)rr * 128 + (((uint32_t)(cc ^ (rr & 7))) << 4);
    }

    auto load_stage = [&](int s, int kt) {
        const uint32_t off = sb + s * STG2;
        #pragma unroll
        for (int j = 0; j < 6; j++)
            CP_ASYNC16(off + dsto[j], srcp[j] + kt);
        CP_COMMIT();
    };

    const uint32_t bbase = 16384 + (uint32_t)p * 16384;
    uint32_t rowoffA[4], rowoffB[2];
    #pragma unroll
    for (int mt = 0; mt < 4; mt++)
        rowoffA[mt] = (uint32_t)(wm + mt * 16 + q1 * 8 + r8) * 128;
    #pragma unroll
    for (int ntp = 0; ntp < 2; ntp++)
        rowoffB[ntp] = (uint32_t)(wn + (ntp * 2 + nsel) * 8 + r8) * 128 + bbase;

    load_stage(0, 0);
    load_stage(1, BK);

    int sub = 0;
    for (int i = 0; i < NCH / 2; i++) {
        CP_WAIT(0);
        __syncthreads();
        if (i < NCH / 2 - 1) {
            load_stage((sub + 2) & 3, (2 * i + 2) * BK);
            load_stage((sub + 3) & 3, (2 * i + 3) * BK);
        }
        #pragma unroll
        for (int hf = 0; hf < 2; hf++) {
            const uint32_t sab = sb + ((sub + hf) & 3) * STG2;
            #pragma unroll
            for (int ks = 0; ks < 4; ks++) {
                uint32_t a[4][4];
                const uint32_t kga = (uint32_t)(((ks << 1) + qa) ^ r8) << 4;
                #pragma unroll
                for (int mt = 0; mt < 4; mt++)
                    ldsm4(a[mt], sab + rowoffA[mt] + kga);
                uint32_t b[4][2];
                const uint32_t kgb = (uint32_t)(((ks << 1) + q1) ^ r8) << 4;
                #pragma unroll
                for (int ntp = 0; ntp < 2; ntp++) {
                    uint32_t bb[4];
                    ldsm4(bb, sab + rowoffB[ntp] + kgb);
                    b[2 * ntp][0] = bb[0]; b[2 * ntp][1] = bb[1];
                    b[2 * ntp + 1][0] = bb[2]; b[2 * ntp + 1][1] = bb[3];
                }
                #pragma unroll
                for (int mt = 0; mt < 4; mt++)
                    #pragma unroll
                    for (int nt = 0; nt < 4; nt++)
                        mma16(c[mt][nt], a[mt], b[nt]);
            }
        }
        sub = (sub + 2) & 3;
    }

    if (task == 0) {
        // xi = prod1 * sigmoid(prod2 + big), fp16 out; smem exchange
        __syncthreads();   // epilogue scratch overlaps stage buffers
        float* sg = (float*)smem;
        if (p == 1) {
            #pragma unroll
            for (int mt = 0; mt < 4; mt++)
                #pragma unroll
                for (int nt = 0; nt < 4; nt++) {
                    const int col = wn + nt * 8 + 2 * t4;
                    const float b0 = big[n0 + col], b1 = big[n0 + col + 1];
                    #pragma unroll
                    for (int h = 0; h < 2; h++) {
                        const int row = wm + mt * 16 + g + h * 8;
                        sg[row * 132 + col]     = sigmoidf_fast(c[mt][nt][2 * h + 0] + b0);
                        sg[row * 132 + col + 1] = sigmoidf_fast(c[mt][nt][2 * h + 1] + b1);
                    }
                }
        }
        __syncthreads();
        if (p == 0) {
            #pragma unroll
            for (int mt = 0; mt < 4; mt++)
                #pragma unroll
                for (int nt = 0; nt < 4; nt++) {
                    const int col = wn + nt * 8 + 2 * t4;
                    #pragma unroll
                    for (int h = 0; h < 2; h++) {
                        const int row = wm + mt * 16 + g + h * 8;
                        const float v0 = c[mt][nt][2 * h + 0] * sg[row * 132 + col];
                        const float v1 = c[mt][nt][2 * h + 1] * sg[row * 132 + col + 1];
                        *(half2*)(out_xi + (size_t)(m0 + row) * NN + n0 + col) =
                            __floats2half2_rn(v0, v1);
                    }
                }
        }
    } else {
        // p==0: r = sigmoid(prod1 + br);  p==1: og = sigmoid(prod2 + bog)  (both fp16)
        const float* bias = p ? bog : br;
        __half* dst = p ? out_og : out_r;
        #pragma unroll
        for (int mt = 0; mt < 4; mt++)
            #pragma unroll
            for (int nt = 0; nt < 4; nt++) {
                const int col = n0 + wn + nt * 8 + 2 * t4;
                const float bb0 = bias[col], bb1 = bias[col + 1];
                #pragma unroll
                for (int h = 0; h < 2; h++) {
                    const int row = m0 + wm + mt * 16 + g + h * 8;
                    const float v0 = sigmoidf_fast(c[mt][nt][2 * h + 0] + bb0);
                    const float v1 = sigmoidf_fast(c[mt][nt][2 * h + 1] + bb1);
                    *(half2*)(dst + (size_t)row * NN + col) = __floats2half2_rn(v0, v1);
                }
            }
    }
}

// ===== NB1W GEMM: out = A@W^T. 512 threads, BM=128, BN=256, warp tile 64x32. =====

#define STG1 49152   // 16KB A + 32KB B per sub-stage

__global__ __launch_bounds__(512, 1)
void gemm_nb1w(const __half* __restrict__ A,
               const __half* __restrict__ W,
               float* __restrict__ out)
{
    extern __shared__ char smem[];
    const uint32_t sb = smem_u32(smem);

    const int tid  = threadIdx.x;
    const int warp = tid >> 5, lane = tid & 31;
    const int m0 = blockIdx.y * 128;
    const int n0 = blockIdx.x * 256;
    const int wm = (warp & 1) * 64;
    const int wn = (warp >> 1) * 32;
    const int g  = lane >> 2, t4 = lane & 3;
    const int r8 = lane & 7;
    const int qa   = (lane >> 4) & 1;
    const int q1   = (lane >> 3) & 1;
    const int nsel = (lane >> 4) & 1;

    float c[4][4][4];
    #pragma unroll
    for (int mt = 0; mt < 4; mt++)
        #pragma unroll
        for (int nt = 0; nt < 4; nt++)
            #pragma unroll
            for (int i = 0; i < 4; i++) c[mt][nt][i] = 0.f;

    const __half* srcp[6];
    uint32_t dsto[6];
    #pragma unroll
    for (int j = 0; j < 6; j++) {
        const int gidx = tid + 512 * j;
        const int rr = gidx >> 3, cc = gidx & 7;
        const __half* base;
        int row;
        if (rr < 128) { base = A; row = m0 + rr; }
        else          { base = W; row = n0 + rr - 128; }
        srcp[j] = base + (size_t)row * NN + cc * 8;
        dsto[j] = (uint32_t)rr * 128 + (((uint32_t)(cc ^ (rr & 7))) << 4);
    }

    auto load_stage = [&](int s, int kt) {
        const uint32_t off = sb + s * STG1;
        #pragma unroll
        for (int j = 0; j < 6; j++)
            CP_ASYNC16(off + dsto[j], srcp[j] + kt);
        CP_COMMIT();
    };

    uint32_t rowoffA[4], rowoffB[2];
    #pragma unroll
    for (int mt = 0; mt < 4; mt++)
        rowoffA[mt] = (uint32_t)(wm + mt * 16 + q1 * 8 + r8) * 128;
    #pragma unroll
    for (int ntp = 0; ntp < 2; ntp++)
        rowoffB[ntp] = (uint32_t)(wn + (ntp * 2 + nsel) * 8 + r8) * 128 + 16384;

    load_stage(0, 0);
    load_stage(1, BK);

    int sub = 0;
    for (int i = 0; i < NCH / 2; i++) {
        CP_WAIT(0);
        __syncthreads();
        if (i < NCH / 2 - 1) {
            load_stage((sub + 2) & 3, (2 * i + 2) * BK);
            load_stage((sub + 3) & 3, (2 * i + 3) * BK);
        }
        #pragma unroll
        for (int hf = 0; hf < 2; hf++) {
            const uint32_t sab = sb + ((sub + hf) & 3) * STG1;
            #pragma unroll
            for (int ks = 0; ks < 4; ks++) {
                uint32_t a[4][4];
                const uint32_t kga = (uint32_t)(((ks << 1) + qa) ^ r8) << 4;
                #pragma unroll
                for (int mt = 0; mt < 4; mt++)
                    ldsm4(a[mt], sab + rowoffA[mt] + kga);
                uint32_t b[4][2];
                const uint32_t kgb = (uint32_t)(((ks << 1) + q1) ^ r8) << 4;
                #pragma unroll
                for (int ntp = 0; ntp < 2; ntp++) {
                    uint32_t bb[4];
                    ldsm4(bb, sab + rowoffB[ntp] + kgb);
                    b[2 * ntp][0] = bb[0]; b[2 * ntp][1] = bb[1];
                    b[2 * ntp + 1][0] = bb[2]; b[2 * ntp + 1][1] = bb[3];
                }
                #pragma unroll
                for (int mt = 0; mt < 4; mt++)
                    #pragma unroll
                    for (int nt = 0; nt < 4; nt++)
                        mma16(c[mt][nt], a[mt], b[nt]);
            }
        }
        sub = (sub + 2) & 3;
    }

    #pragma unroll
    for (int mt = 0; mt < 4; mt++)
        #pragma unroll
        for (int nt = 0; nt < 4; nt++) {
            const int col = n0 + wn + nt * 8 + 2 * t4;
            #pragma unroll
            for (int h = 0; h < 2; h++) {
                const int row = m0 + wm + mt * 16 + g + h * 8;
                *(float2*)(out + (size_t)row * NN + col) =
                    make_float2(c[mt][nt][2 * h + 0], c[mt][nt][2 * h + 1]);
            }
        }
}

// ================= chunked associative scan (CT=16, fp16 streams) =================

__global__ __launch_bounds__(512)
void scan_passA()
{
    const int bj = blockIdx.x;            // b*NC + j, 1024 blocks
    const int b  = bj / NC, j = bj % NC;
    const int m2 = threadIdx.x * 2;
    const size_t base = ((size_t)b * TT + (size_t)j * CT) * NN + m2;
    float2 Aacc = make_float2(1.f, 1.f);
    float2 h    = make_float2(0.f, 0.f);
    #pragma unroll
    for (int t = 0; t < CT; t++) {
        const size_t o = base + (size_t)t * NN;
        const float2 rv = __half22float2(*(const __half2*)(g_rh  + o));
        const float2 xv = __half22float2(*(const __half2*)(g_xih + o));
        h.x = h.x * rv.x + xv.x;
        h.y = h.y * rv.y + xv.y;
        Aacc.x *= rv.x;
        Aacc.y *= rv.y;
    }
    const size_t ci = (size_t)bj * NN + m2;
    *(float2*)(g_cA + ci) = Aacc;
    *(float2*)(g_cB + ci) = h;
}

// chunk-prefix: latency-pipelined batched prefetch (groups of 8, double-buffered).
// 2 channels/thread (float2); grid (BB, 4) x 128 threads = 8192 channels.
__global__ __launch_bounds__(128)
void scan_mid(const float* __restrict__ mem)
{
    const int b  = blockIdx.x;
    const int m2 = (blockIdx.y * 128 + threadIdx.x) * 2;
    const size_t cbase = (size_t)b * NC * NN + m2;

    float2 h = *(const float2*)(mem + b * NN + m2);
    float2 a[2][8], bv[2][8];

    // prefetch group 0
    #pragma unroll
    for (int u = 0; u < 8; u++) {
        const size_t ci = cbase + (size_t)u * NN;
        a[0][u]  = *(const float2*)(g_cA + ci);
        bv[0][u] = *(const float2*)(g_cB + ci);
    }
    #pragma unroll
    for (int gq = 0; gq < NC / 8; gq++) {
        const int cur = gq & 1;
        if (gq + 1 < NC / 8) {
            const size_t nb = cbase + (size_t)(gq + 1) * 8 * NN;
            #pragma unroll
            for (int u = 0; u < 8; u++) {
                const size_t ci = nb + (size_t)u * NN;
                a[cur ^ 1][u]  = *(const float2*)(g_cA + ci);
                bv[cur ^ 1][u] = *(const float2*)(g_cB + ci);
            }
        }
        const size_t gb = cbase + (size_t)gq * 8 * NN;
        #pragma unroll
        for (int u = 0; u < 8; u++) {
            *(float2*)(g_cH + gb + (size_t)u * NN) = h;
            h.x = a[cur][u].x * h.x + bv[cur][u].x;
            h.y = a[cur][u].y * h.y + bv[cur][u].y;
        }
    }
}

__global__ __launch_bounds__(512)
void scan_passB(float* __restrict__ memout)
{
    const int bj = blockIdx.x;
    const int b  = bj / NC, j = bj % NC;
    const int m2 = threadIdx.x * 2;
    const size_t base = ((size_t)b * TT + (size_t)j * CT) * NN + m2;
    float2 h = *(const float2*)(g_cH + (size_t)bj * NN + m2);
    #pragma unroll
    for (int t = 0; t < CT; t++) {
        const size_t o = base + (size_t)t * NN;
        const float2 rv = __half22float2(*(const __half2*)(g_rh  + o));
        const float2 xv = __half22float2(*(const __half2*)(g_xih + o));
        const float2 ov = __half22float2(*(const __half2*)(g_ogh + o));
        h.x = h.x * rv.x + xv.x;
        h.y = h.y * rv.y + xv.y;
        const float y0 = (h.x / (1.f + fabsf(h.x))) * ov.x;
        const float y1 = (h.y / (1.f + fabsf(h.y))) * ov.y;
        *(half2*)(g_yh + o) = __floats2half2_rn(y0, y1);
    }
    if (j == NC - 1) *(float2*)(memout + b * NN + m2) = h;
}

// ================= host =================

extern "C" void kernel_launch(void* const* d_in, const int* in_sizes, int n_in,
                              void* d_out, int out_size)
{
    const float* x     = (const float*)d_in[0];
    const float* mem   = (const float*)d_in[1];
    const float* wr_w  = (const float*)d_in[2];
    const float* wr_b  = (const float*)d_in[3];
    const float* wi_w  = (const float*)d_in[4];
    const float* wig_w = (const float*)d_in[5];
    const float* wig_b = (const float*)d_in[6];
    const float* wog_w = (const float*)d_in[7];
    const float* wog_b = (const float*)d_in[8];
    const float* wo_w  = (const float*)d_in[9];

    float* out     = (float*)d_out;
    float* y_out   = out;
    float* mem_out = out + (size_t)MTOT * NN;

    __half *p_rh, *p_xih, *p_ogh, *p_xh, *p_yh, *p_wh;
    cudaGetSymbolAddress((void**)&p_rh,  g_rh);
    cudaGetSymbolAddress((void**)&p_xih, g_xih);
    cudaGetSymbolAddress((void**)&p_ogh, g_ogh);
    cudaGetSymbolAddress((void**)&p_xh,  g_xh);
    cudaGetSymbolAddress((void**)&p_yh,  g_yh);
    cudaGetSymbolAddress((void**)&p_wh,  g_wh);

    __half* wh_r  = p_wh + 0 * (size_t)NN * NN;
    __half* wh_i  = p_wh + 1 * (size_t)NN * NN;
    __half* wh_ig = p_wh + 2 * (size_t)NN * NN;
    __half* wh_og = p_wh + 3 * (size_t)NN * NN;
    __half* wh_o  = p_wh + 4 * (size_t)NN * NN;

    constexpr int SMEM = 4 * STG2;   // 192KB, 4 sub-stages
    cudaFuncSetAttribute(gemm_proj, cudaFuncAttributeMaxDynamicSharedMemorySize, SMEM);
    cudaFuncSetAttribute(gemm_nb1w, cudaFuncAttributeMaxDynamicSharedMemorySize, SMEM);

    dim3 ggp(NN / 128, MTOT / 128, 2);   // (8, 128, 2)
    dim3 gg1(NN / 256, MTOT / 128);      // (4, 128)

    cvt_all<<<2688, 256>>>(x, wr_w, wi_w, wig_w, wog_w, wo_w, p_xh, p_wh);  // 0
    gemm_proj<<<ggp, 512, SMEM>>>(p_xh, wh_i, wh_ig, wh_r, wh_og,           // 1
                                  wig_b, wr_b, wog_b, p_rh, p_xih, p_ogh);
    scan_passA<<<BB * NC, 512>>>();                                         // 2
    scan_mid<<<dim3(BB, 4), 128>>>(mem);                                    // 3 (PROFILED)
    scan_passB<<<BB * NC, 512>>>(mem_out);                                  // 4
    gemm_nb1w<<<gg1, 512, SMEM>>>(p_yh, wh_o, y_out);                       // 5
}